// round 1
// baseline (speedup 1.0000x reference)
#include <cuda_runtime.h>

#define NSRC 50000
#define NTGT 10000
#define EE   250000
#define NLBL 200000

// ---------------- scratch (static device globals; no runtime allocation) ----------------
__device__ float g_xs[2][NSRC * 64];
__device__ float g_xt[2][NTGT * 64];
__device__ float g_q[NSRC * 256];
__device__ float g_k[NSRC * 256];
__device__ float g_v[NSRC * 256];
__device__ int   g_rp_st[NTGT + 1];
__device__ int   g_col_st[EE];
__device__ int   g_rp_ts[NSRC + 1];
__device__ int   g_col_ts[EE];
__device__ int   g_cnt[NSRC];

// ---------------- small utility kernels ----------------
__global__ void k_gather(const float* __restrict__ emb, const int* __restrict__ ids,
                         float* __restrict__ out, int nrows) {
    int t = blockIdx.x * blockDim.x + threadIdx.x;
    int total = nrows * 16;
    if (t >= total) return;
    int r = t >> 4, c = t & 15;
    ((float4*)out)[r * 16 + c] = ((const float4*)emb)[ids[r] * 16 + c];
}

__global__ void k_zero_int(int* p, int n) {
    int t = blockIdx.x * blockDim.x + threadIdx.x;
    if (t < n) p[t] = 0;
}

__global__ void k_copy_int(const int* __restrict__ a, int* __restrict__ b, int n) {
    int t = blockIdx.x * blockDim.x + threadIdx.x;
    if (t < n) b[t] = a[t];
}

__global__ void k_count(const int* __restrict__ dst, int* cnt, int E) {
    int t = blockIdx.x * blockDim.x + threadIdx.x;
    if (t < E) atomicAdd(&cnt[dst[t]], 1);
}

// single-block exclusive scan (n <= 50000, runs twice per launch; cheap)
__global__ void k_scan(const int* __restrict__ deg, int* __restrict__ rowptr, int n) {
    __shared__ int sh[1024];
    __shared__ int sbase;
    int tid = threadIdx.x;
    if (tid == 0) sbase = 0;
    __syncthreads();
    for (int chunk = 0; chunk < n; chunk += 1024) {
        int i = chunk + tid;
        int val = (i < n) ? deg[i] : 0;
        sh[tid] = val;
        __syncthreads();
        for (int off = 1; off < 1024; off <<= 1) {
            int t = (tid >= off) ? sh[tid - off] : 0;
            __syncthreads();
            sh[tid] += t;
            __syncthreads();
        }
        if (i < n) rowptr[i] = sbase + sh[tid] - val;   // exclusive
        __syncthreads();
        if (tid == 0) sbase += sh[1023];
        __syncthreads();
    }
    if (tid == 0) rowptr[n] = sbase;
}

__global__ void k_scatter(const int* __restrict__ src, const int* __restrict__ dst,
                          int* cursor, int* __restrict__ colout, int E) {
    int t = blockIdx.x * blockDim.x + threadIdx.x;
    if (t < E) {
        int d = dst[t];
        int pos = atomicAdd(&cursor[d], 1);
        colout[pos] = src[t];
    }
}

// ---------------- GEMM: C[N,ncols] = X[N,64] @ W[64,ncols] + B ----------------
// 64x64 tile, 256 threads, 4x4 microtile per thread, full K=64 staged in smem.
__global__ void k_gemm(const float* __restrict__ X, int N,
                       const float* __restrict__ W, const float* __restrict__ B,
                       float* __restrict__ C, int ncols) {
    __shared__ float xs[64][68];  // row-major X tile (68: float4-aligned rows)
    __shared__ float ws[64][68];  // W tile: ws[k][c]
    int tid = threadIdx.x;
    int row0 = blockIdx.x << 6;
    int col0 = blockIdx.y << 6;

#pragma unroll
    for (int i = 0; i < 4; i++) {
        int idx = tid + (i << 8);           // 0..1023
        int r = idx >> 4, c4 = idx & 15;
        float4 val = make_float4(0.f, 0.f, 0.f, 0.f);
        if (row0 + r < N) val = *(const float4*)(X + (row0 + r) * 64 + (c4 << 2));
        *(float4*)&xs[r][c4 << 2] = val;
        *(float4*)&ws[r][c4 << 2] = *(const float4*)(W + r * ncols + col0 + (c4 << 2));
    }
    __syncthreads();

    int tx = tid & 15, ty = tid >> 4;
    float acc[4][4];
#pragma unroll
    for (int i = 0; i < 4; i++)
#pragma unroll
        for (int j = 0; j < 4; j++) acc[i][j] = 0.f;

#pragma unroll
    for (int kk = 0; kk < 64; kk++) {
        float4 wv = *(const float4*)&ws[kk][tx << 2];
        float a0 = xs[(ty << 2) + 0][kk];
        float a1 = xs[(ty << 2) + 1][kk];
        float a2 = xs[(ty << 2) + 2][kk];
        float a3 = xs[(ty << 2) + 3][kk];
        acc[0][0] += a0 * wv.x; acc[0][1] += a0 * wv.y; acc[0][2] += a0 * wv.z; acc[0][3] += a0 * wv.w;
        acc[1][0] += a1 * wv.x; acc[1][1] += a1 * wv.y; acc[1][2] += a1 * wv.z; acc[1][3] += a1 * wv.w;
        acc[2][0] += a2 * wv.x; acc[2][1] += a2 * wv.y; acc[2][2] += a2 * wv.z; acc[2][3] += a2 * wv.w;
        acc[3][0] += a3 * wv.x; acc[3][1] += a3 * wv.y; acc[3][2] += a3 * wv.z; acc[3][3] += a3 * wv.w;
    }

    float4 bb = *(const float4*)(B + col0 + (tx << 2));
#pragma unroll
    for (int i = 0; i < 4; i++) {
        int r = row0 + (ty << 2) + i;
        if (r < N) {
            float4 o;
            o.x = acc[i][0] + bb.x; o.y = acc[i][1] + bb.y;
            o.z = acc[i][2] + bb.z; o.w = acc[i][3] + bb.w;
            *(float4*)(C + r * ncols + col0 + (tx << 2)) = o;
        }
    }
}

// ---------------- fused per-dst attention (softmax + weighted aggregation) ----------------
// One warp per dst node. Lane l holds flat channels [l*8, l*8+8) of the 256 = 4 heads x 64.
// Head = lane>>3; per-head dot via xor-shuffle over 8 lanes. No max-subtraction needed
// (scores are O(1-10)); denom==0 guard handles zero-in-degree nodes.
__global__ void k_attn(const int* __restrict__ rowptr, const int* __restrict__ col,
                       const float* __restrict__ Q, const float* __restrict__ K,
                       const float* __restrict__ V, float* __restrict__ out,
                       int ndst, int do_relu) {
    int w = (blockIdx.x * blockDim.x + threadIdx.x) >> 5;
    if (w >= ndst) return;
    int lane = threadIdx.x & 31;

    const float4* qp = (const float4*)(Q + w * 256 + lane * 8);
    float4 q0 = qp[0], q1 = qp[1];

    float a0 = 0.f, a1 = 0.f, a2 = 0.f, a3 = 0.f, a4 = 0.f, a5 = 0.f, a6 = 0.f, a7 = 0.f;
    float denom = 0.f;
    int e0 = rowptr[w], e1 = rowptr[w + 1];

    for (int e = e0; e < e1; ++e) {
        int s = col[e];
        const float4* kp = (const float4*)(K + s * 256 + lane * 8);
        const float4* vp = (const float4*)(V + s * 256 + lane * 8);
        float4 k0 = kp[0], k1 = kp[1];
        float4 v0 = vp[0], v1 = vp[1];
        float p = q0.x * k0.x + q0.y * k0.y + q0.z * k0.z + q0.w * k0.w
                + q1.x * k1.x + q1.y * k1.y + q1.z * k1.z + q1.w * k1.w;
        p += __shfl_xor_sync(0xffffffffu, p, 1);
        p += __shfl_xor_sync(0xffffffffu, p, 2);
        p += __shfl_xor_sync(0xffffffffu, p, 4);
        float wgt = __expf(p * 0.125f);     // 1/sqrt(64)
        denom += wgt;
        a0 += wgt * v0.x; a1 += wgt * v0.y; a2 += wgt * v0.z; a3 += wgt * v0.w;
        a4 += wgt * v1.x; a5 += wgt * v1.y; a6 += wgt * v1.z; a7 += wgt * v1.w;
    }

    float inv = (denom > 0.f) ? (0.25f / denom) : 0.f;  // fold head-mean (/4) in
    a0 *= inv; a1 *= inv; a2 *= inv; a3 *= inv;
    a4 *= inv; a5 *= inv; a6 *= inv; a7 *= inv;

    // sum over the 4 heads: lanes l, l^8, l^16|l^24 hold the same channel d=(l&7)*8+j
#define HEADRED(x) x += __shfl_xor_sync(0xffffffffu, x, 8); x += __shfl_xor_sync(0xffffffffu, x, 16);
    HEADRED(a0) HEADRED(a1) HEADRED(a2) HEADRED(a3)
    HEADRED(a4) HEADRED(a5) HEADRED(a6) HEADRED(a7)
#undef HEADRED

    if (lane < 8) {
        float* op = out + w * 64 + lane * 8;   // holds skip (x_dst @ Ws + bs)
        float r[8] = {a0, a1, a2, a3, a4, a5, a6, a7};
#pragma unroll
        for (int j = 0; j < 8; j++) {
            float val = r[j] + op[j];
            if (do_relu) val = fmaxf(val, 0.f);
            op[j] = val;
        }
    }
}

// ---------------- classifier: pred[i] = dot(xs[a], xt[b]) ----------------
__global__ void k_classify(const float* __restrict__ xs, const float* __restrict__ xt,
                           const int* __restrict__ li, float* __restrict__ out, int n) {
    int t = blockIdx.x * blockDim.x + threadIdx.x;
    if (t >= n) return;
    int a = li[t], b = li[n + t];
    const float4* pa = (const float4*)(xs + a * 64);
    const float4* pb = (const float4*)(xt + b * 64);
    float s = 0.f;
#pragma unroll
    for (int j = 0; j < 16; j++) {
        float4 x = pa[j], y = pb[j];
        s += x.x * y.x + x.y * y.y + x.z * y.z + x.w * y.w;
    }
    out[t] = s;
}

// ---------------- launch ----------------
extern "C" void kernel_launch(void* const* d_in, const int* in_sizes, int n_in,
                              void* d_out, int out_size) {
    const float* src_emb = (const float*)d_in[0];
    const float* tgt_emb = (const float*)d_in[1];
    const float* Wq = (const float*)d_in[2];
    const float* bq = (const float*)d_in[3];
    const float* Wk = (const float*)d_in[4];
    const float* bk = (const float*)d_in[5];
    const float* Wv = (const float*)d_in[6];
    const float* bv = (const float*)d_in[7];
    const float* Ws = (const float*)d_in[8];
    const float* bs = (const float*)d_in[9];
    const int* nid_s = (const int*)d_in[10];
    const int* nid_t = (const int*)d_in[11];
    const int* e_st = (const int*)d_in[12];   // [2, E]: row0 = src ids, row1 = dst ids
    const int* e_ts = (const int*)d_in[13];
    const int* lbl  = (const int*)d_in[14];   // [2, N_LBL]
    float* outp = (float*)d_out;

    float *xsA, *xtA, *q, *k, *v;
    int *rp_st, *col_st, *rp_ts, *col_ts, *cnt;
    cudaGetSymbolAddress((void**)&xsA, g_xs);
    cudaGetSymbolAddress((void**)&xtA, g_xt);
    cudaGetSymbolAddress((void**)&q, g_q);
    cudaGetSymbolAddress((void**)&k, g_k);
    cudaGetSymbolAddress((void**)&v, g_v);
    cudaGetSymbolAddress((void**)&rp_st, g_rp_st);
    cudaGetSymbolAddress((void**)&col_st, g_col_st);
    cudaGetSymbolAddress((void**)&rp_ts, g_rp_ts);
    cudaGetSymbolAddress((void**)&col_ts, g_col_ts);
    cudaGetSymbolAddress((void**)&cnt, g_cnt);

    float* xs0 = xsA;
    float* xs1 = xsA + NSRC * 64;
    float* xt0 = xtA;
    float* xt1 = xtA + NTGT * 64;

    // initial node features (identity gather per node_id arrays)
    k_gather<<<(NSRC * 16 + 255) / 256, 256>>>(src_emb, nid_s, xs0, NSRC);
    k_gather<<<(NTGT * 16 + 255) / 256, 256>>>(tgt_emb, nid_t, xt0, NTGT);

    // CSR for edge_st (group by dst in [0, NTGT))
    k_zero_int<<<(NTGT + 255) / 256, 256>>>(cnt, NTGT);
    k_count<<<(EE + 255) / 256, 256>>>(e_st + EE, cnt, EE);
    k_scan<<<1, 1024>>>(cnt, rp_st, NTGT);
    k_copy_int<<<(NTGT + 255) / 256, 256>>>(rp_st, cnt, NTGT);
    k_scatter<<<(EE + 255) / 256, 256>>>(e_st, e_st + EE, cnt, col_st, EE);

    // CSR for edge_ts (group by dst in [0, NSRC))
    k_zero_int<<<(NSRC + 255) / 256, 256>>>(cnt, NSRC);
    k_count<<<(EE + 255) / 256, 256>>>(e_ts + EE, cnt, EE);
    k_scan<<<1, 1024>>>(cnt, rp_ts, NSRC);
    k_copy_int<<<(NSRC + 255) / 256, 256>>>(rp_ts, cnt, NSRC);
    k_scatter<<<(EE + 255) / 256, 256>>>(e_ts, e_ts + EE, cnt, col_ts, EE);

    dim3 g256s((NSRC + 63) / 64, 4), g256t((NTGT + 63) / 64, 4);
    dim3 g64s((NSRC + 63) / 64, 1), g64t((NTGT + 63) / 64, 1);

    for (int l = 0; l < 2; l++) {
        float* xs_cur = (l == 0) ? xs0 : xs1;
        float* xt_cur = (l == 0) ? xt0 : xt1;
        float* xs_nxt = (l == 0) ? xs1 : xs0;
        float* xt_nxt = (l == 0) ? xt1 : xt0;
        int relu = (l == 0) ? 1 : 0;
        int p0 = l * 2 + 0, p1 = l * 2 + 1;

        // ---- tconv st: src = xs_cur (NSRC), dst = xt_cur (NTGT), params (l,0) ----
        k_gemm<<<g256s, 256>>>(xs_cur, NSRC, Wk + p0 * 64 * 256, bk + p0 * 256, k, 256);
        k_gemm<<<g256s, 256>>>(xs_cur, NSRC, Wv + p0 * 64 * 256, bv + p0 * 256, v, 256);
        k_gemm<<<g256t, 256>>>(xt_cur, NTGT, Wq + p0 * 64 * 256, bq + p0 * 256, q, 256);
        k_gemm<<<g64t, 256>>>(xt_cur, NTGT, Ws + p0 * 4096, bs + p0 * 64, xt_nxt, 64);
        k_attn<<<(NTGT + 7) / 8, 256>>>(rp_st, col_st, q, k, v, xt_nxt, NTGT, relu);

        // ---- tconv ts: src = xt_cur (NTGT), dst = xs_cur (NSRC), params (l,1) ----
        k_gemm<<<g256t, 256>>>(xt_cur, NTGT, Wk + p1 * 64 * 256, bk + p1 * 256, k, 256);
        k_gemm<<<g256t, 256>>>(xt_cur, NTGT, Wv + p1 * 64 * 256, bv + p1 * 256, v, 256);
        k_gemm<<<g256s, 256>>>(xs_cur, NSRC, Wq + p1 * 64 * 256, bq + p1 * 256, q, 256);
        k_gemm<<<g64s, 256>>>(xs_cur, NSRC, Ws + p1 * 4096, bs + p1 * 64, xs_nxt, 64);
        k_attn<<<(NSRC + 7) / 8, 256>>>(rp_ts, col_ts, q, k, v, xs_nxt, NSRC, relu);
    }

    // after l=1 the final features live in buffer 0
    k_classify<<<(NLBL + 255) / 256, 256>>>(xs0, xt0, lbl, outp, NLBL);
}

// round 2
// speedup vs baseline: 1.0237x; 1.0237x over previous
#include <cuda_runtime.h>
#include <cstdint>

#define NSRC 50000
#define NTGT 10000
#define EE   250000
#define NLBL 200000

// ---------------- scratch (static device globals; no runtime allocation) ----------------
__device__ float g_xs[2][NSRC * 64];
__device__ float g_xt[2][NTGT * 64];
__device__ float g_q[NSRC * 256];
__device__ float g_k[NSRC * 256];
__device__ float g_v[NSRC * 256];
__device__ int   g_rp_st[NTGT + 1];
__device__ int   g_col_st[EE];
__device__ int   g_rp_ts[NSRC + 1];
__device__ int   g_col_ts[EE];
__device__ int   g_cnt[NSRC];

// ---------------- small utility kernels ----------------
__global__ void k_gather(const float* __restrict__ emb, const int* __restrict__ ids,
                         float* __restrict__ out, int nrows) {
    int t = blockIdx.x * blockDim.x + threadIdx.x;
    int total = nrows * 16;
    if (t >= total) return;
    int r = t >> 4, c = t & 15;
    ((float4*)out)[r * 16 + c] = ((const float4*)emb)[ids[r] * 16 + c];
}

__global__ void k_zero_int(int* p, int n) {
    int t = blockIdx.x * blockDim.x + threadIdx.x;
    if (t < n) p[t] = 0;
}

__global__ void k_copy_int(const int* __restrict__ a, int* __restrict__ b, int n) {
    int t = blockIdx.x * blockDim.x + threadIdx.x;
    if (t < n) b[t] = a[t];
}

__global__ void k_count(const int* __restrict__ dst, int* cnt, int E) {
    int t = blockIdx.x * blockDim.x + threadIdx.x;
    if (t < E) atomicAdd(&cnt[dst[t]], 1);
}

// single-block exclusive scan, warp-shuffle based (2 syncs per 1024-chunk)
__global__ void k_scan(const int* __restrict__ deg, int* __restrict__ rowptr, int n) {
    __shared__ int warpsums[32];
    __shared__ int sbase;
    int tid = threadIdx.x, lane = tid & 31, wid = tid >> 5;
    if (tid == 0) sbase = 0;
    __syncthreads();
    for (int chunk = 0; chunk < n; chunk += 1024) {
        int i = chunk + tid;
        int v = (i < n) ? deg[i] : 0;
        int x = v;
#pragma unroll
        for (int off = 1; off < 32; off <<= 1) {
            int y = __shfl_up_sync(0xffffffffu, x, off);
            if (lane >= off) x += y;
        }
        if (lane == 31) warpsums[wid] = x;
        __syncthreads();
        if (wid == 0) {
            int s = warpsums[lane];
#pragma unroll
            for (int off = 1; off < 32; off <<= 1) {
                int y = __shfl_up_sync(0xffffffffu, s, off);
                if (lane >= off) s += y;
            }
            warpsums[lane] = s;
        }
        __syncthreads();
        int wbase = (wid > 0) ? warpsums[wid - 1] : 0;
        if (i < n) rowptr[i] = sbase + wbase + x - v;   // exclusive
        int total = warpsums[31];
        __syncthreads();
        if (tid == 0) sbase += total;
        __syncthreads();
    }
    if (tid == 0) rowptr[n] = sbase;
}

__global__ void k_scatter(const int* __restrict__ src, const int* __restrict__ dst,
                          int* cursor, int* __restrict__ colout, int E) {
    int t = blockIdx.x * blockDim.x + threadIdx.x;
    if (t < E) {
        int d = dst[t];
        int pos = atomicAdd(&cursor[d], 1);
        colout[pos] = src[t];
    }
}

// ---------------- tensor-core GEMM (3xTF32): C[N,ncols] = X[N,64] @ W[64,ncols] + B ----
__device__ __forceinline__ float tf32r(float x) {
    uint32_t u;
    asm("cvt.rna.tf32.f32 %0, %1;" : "=r"(u) : "f"(x));
    return __uint_as_float(u);
}
__device__ __forceinline__ uint32_t f2u(float x) { return __float_as_uint(x); }

__device__ __forceinline__ void mma_tf32(float* c, const uint32_t* a, const uint32_t* b) {
    asm volatile(
        "mma.sync.aligned.m16n8k8.row.col.f32.tf32.tf32.f32 "
        "{%0,%1,%2,%3}, {%4,%5,%6,%7}, {%8,%9}, {%0,%1,%2,%3};"
        : "+f"(c[0]), "+f"(c[1]), "+f"(c[2]), "+f"(c[3])
        : "r"(a[0]), "r"(a[1]), "r"(a[2]), "r"(a[3]), "r"(b[0]), "r"(b[1]));
}

#define GS 68   // float2 stride per smem row (word-stride 136 % 32 == 8: conflict-free frags)
#define GEMM_SMEM (2 * 64 * GS * (int)sizeof(float2))

// block: 128 threads (4 warps). tile: M=64 (16/warp), N=64, K=64 (single stage).
__global__ void k_gemm_tc(const float* __restrict__ X, int N,
                          const float* __restrict__ W, const float* __restrict__ Bv,
                          float* __restrict__ C, int ncols) {
    extern __shared__ unsigned char smemraw[];
    float2 (*sX)[GS] = (float2(*)[GS])smemraw;                       // [m][k] {hi,lo}
    float2 (*sW)[GS] = (float2(*)[GS])(smemraw + 64 * GS * sizeof(float2)); // [k][n] {hi,lo}

    int tid = threadIdx.x;
    int row0 = blockIdx.x << 6, col0 = blockIdx.y << 6;

    // stage + split X tile [64x64] and W tile [64x64]
#pragma unroll
    for (int i = 0; i < 8; i++) {
        int idx = tid + (i << 7);            // 0..1023 float4 slots
        int r = idx >> 4, c4 = (idx & 15) << 2;
        float4 xv = make_float4(0.f, 0.f, 0.f, 0.f);
        if (row0 + r < N) xv = *(const float4*)(X + (row0 + r) * 64 + c4);
        float4 wv = *(const float4*)(W + r * ncols + col0 + c4);

        float hx = tf32r(xv.x), hy = tf32r(xv.y), hz = tf32r(xv.z), hw = tf32r(xv.w);
        sX[r][c4 + 0] = make_float2(hx, tf32r(xv.x - hx));
        sX[r][c4 + 1] = make_float2(hy, tf32r(xv.y - hy));
        sX[r][c4 + 2] = make_float2(hz, tf32r(xv.z - hz));
        sX[r][c4 + 3] = make_float2(hw, tf32r(xv.w - hw));

        float gx = tf32r(wv.x), gy = tf32r(wv.y), gz = tf32r(wv.z), gw = tf32r(wv.w);
        sW[r][c4 + 0] = make_float2(gx, tf32r(wv.x - gx));
        sW[r][c4 + 1] = make_float2(gy, tf32r(wv.y - gy));
        sW[r][c4 + 2] = make_float2(gz, tf32r(wv.z - gz));
        sW[r][c4 + 3] = make_float2(gw, tf32r(wv.w - gw));
    }
    __syncthreads();

    int lane = tid & 31, warp = tid >> 5;
    int gid = lane >> 2, tig = lane & 3;
    int m0 = warp << 4;

    float acc[8][4];
#pragma unroll
    for (int nt = 0; nt < 8; nt++)
#pragma unroll
        for (int j = 0; j < 4; j++) acc[nt][j] = 0.f;

#pragma unroll
    for (int kk = 0; kk < 8; kk++) {
        int k0 = kk << 3;
        uint32_t ahi[4], alo[4];
        float2 t;
        t = sX[m0 + gid][k0 + tig];         ahi[0] = f2u(t.x); alo[0] = f2u(t.y);
        t = sX[m0 + gid + 8][k0 + tig];     ahi[1] = f2u(t.x); alo[1] = f2u(t.y);
        t = sX[m0 + gid][k0 + tig + 4];     ahi[2] = f2u(t.x); alo[2] = f2u(t.y);
        t = sX[m0 + gid + 8][k0 + tig + 4]; ahi[3] = f2u(t.x); alo[3] = f2u(t.y);
#pragma unroll
        for (int nt = 0; nt < 8; nt++) {
            float2 b0 = sW[k0 + tig][(nt << 3) + gid];
            float2 b1 = sW[k0 + tig + 4][(nt << 3) + gid];
            uint32_t bhi[2] = { f2u(b0.x), f2u(b1.x) };
            uint32_t blo[2] = { f2u(b0.y), f2u(b1.y) };
            mma_tf32(acc[nt], ahi, bhi);
            mma_tf32(acc[nt], alo, bhi);
            mma_tf32(acc[nt], ahi, blo);
        }
    }

    // epilogue: + bias, store
#pragma unroll
    for (int nt = 0; nt < 8; nt++) {
        int col = col0 + (nt << 3) + (tig << 1);
        float2 bias = *(const float2*)(Bv + col);
        int r = row0 + m0 + gid;
        if (r < N) {
            float2 o = make_float2(acc[nt][0] + bias.x, acc[nt][1] + bias.y);
            *(float2*)(C + r * ncols + col) = o;
        }
        r += 8;
        if (r < N) {
            float2 o = make_float2(acc[nt][2] + bias.x, acc[nt][3] + bias.y);
            *(float2*)(C + r * ncols + col) = o;
        }
    }
}

// ---------------- fused per-dst attention (softmax + weighted aggregation) ----------------
__global__ void k_attn(const int* __restrict__ rowptr, const int* __restrict__ col,
                       const float* __restrict__ Q, const float* __restrict__ K,
                       const float* __restrict__ V, float* __restrict__ out,
                       int ndst, int do_relu) {
    int w = (blockIdx.x * blockDim.x + threadIdx.x) >> 5;
    if (w >= ndst) return;
    int lane = threadIdx.x & 31;

    const float4* qp = (const float4*)(Q + w * 256 + lane * 8);
    float4 q0 = qp[0], q1 = qp[1];

    float a0 = 0.f, a1 = 0.f, a2 = 0.f, a3 = 0.f, a4 = 0.f, a5 = 0.f, a6 = 0.f, a7 = 0.f;
    float denom = 0.f;
    int e0 = rowptr[w], e1 = rowptr[w + 1];

    for (int e = e0; e < e1; ++e) {
        int s = col[e];
        const float4* kp = (const float4*)(K + s * 256 + lane * 8);
        const float4* vp = (const float4*)(V + s * 256 + lane * 8);
        float4 k0 = kp[0], k1 = kp[1];
        float4 v0 = vp[0], v1 = vp[1];
        float p = q0.x * k0.x + q0.y * k0.y + q0.z * k0.z + q0.w * k0.w
                + q1.x * k1.x + q1.y * k1.y + q1.z * k1.z + q1.w * k1.w;
        p += __shfl_xor_sync(0xffffffffu, p, 1);
        p += __shfl_xor_sync(0xffffffffu, p, 2);
        p += __shfl_xor_sync(0xffffffffu, p, 4);
        float wgt = __expf(p * 0.125f);     // 1/sqrt(64)
        denom += wgt;
        a0 += wgt * v0.x; a1 += wgt * v0.y; a2 += wgt * v0.z; a3 += wgt * v0.w;
        a4 += wgt * v1.x; a5 += wgt * v1.y; a6 += wgt * v1.z; a7 += wgt * v1.w;
    }

    float inv = (denom > 0.f) ? (0.25f / denom) : 0.f;  // fold head-mean (/4) in
    a0 *= inv; a1 *= inv; a2 *= inv; a3 *= inv;
    a4 *= inv; a5 *= inv; a6 *= inv; a7 *= inv;

#define HEADRED(x) x += __shfl_xor_sync(0xffffffffu, x, 8); x += __shfl_xor_sync(0xffffffffu, x, 16);
    HEADRED(a0) HEADRED(a1) HEADRED(a2) HEADRED(a3)
    HEADRED(a4) HEADRED(a5) HEADRED(a6) HEADRED(a7)
#undef HEADRED

    if (lane < 8) {
        float* op = out + w * 64 + lane * 8;   // holds skip (x_dst @ Ws + bs)
        float r[8] = {a0, a1, a2, a3, a4, a5, a6, a7};
#pragma unroll
        for (int j = 0; j < 8; j++) {
            float val = r[j] + op[j];
            if (do_relu) val = fmaxf(val, 0.f);
            op[j] = val;
        }
    }
}

// ---------------- classifier: pred[i] = dot(xs[a], xt[b]) ----------------
__global__ void k_classify(const float* __restrict__ xs, const float* __restrict__ xt,
                           const int* __restrict__ li, float* __restrict__ out, int n) {
    int t = blockIdx.x * blockDim.x + threadIdx.x;
    if (t >= n) return;
    int a = li[t], b = li[n + t];
    const float4* pa = (const float4*)(xs + a * 64);
    const float4* pb = (const float4*)(xt + b * 64);
    float s = 0.f;
#pragma unroll
    for (int j = 0; j < 16; j++) {
        float4 x = pa[j], y = pb[j];
        s += x.x * y.x + x.y * y.y + x.z * y.z + x.w * y.w;
    }
    out[t] = s;
}

// ---------------- launch ----------------
extern "C" void kernel_launch(void* const* d_in, const int* in_sizes, int n_in,
                              void* d_out, int out_size) {
    const float* src_emb = (const float*)d_in[0];
    const float* tgt_emb = (const float*)d_in[1];
    const float* Wq = (const float*)d_in[2];
    const float* bq = (const float*)d_in[3];
    const float* Wk = (const float*)d_in[4];
    const float* bk = (const float*)d_in[5];
    const float* Wv = (const float*)d_in[6];
    const float* bv = (const float*)d_in[7];
    const float* Ws = (const float*)d_in[8];
    const float* bs = (const float*)d_in[9];
    const int* nid_s = (const int*)d_in[10];
    const int* nid_t = (const int*)d_in[11];
    const int* e_st = (const int*)d_in[12];   // [2, E]: row0 = src ids, row1 = dst ids
    const int* e_ts = (const int*)d_in[13];
    const int* lbl  = (const int*)d_in[14];   // [2, N_LBL]
    float* outp = (float*)d_out;

    static int attr_done = 0;
    if (!attr_done) {
        cudaFuncSetAttribute(k_gemm_tc, cudaFuncAttributeMaxDynamicSharedMemorySize, GEMM_SMEM);
        attr_done = 1;
    }

    float *xsA, *xtA, *q, *k, *v;
    int *rp_st, *col_st, *rp_ts, *col_ts, *cnt;
    cudaGetSymbolAddress((void**)&xsA, g_xs);
    cudaGetSymbolAddress((void**)&xtA, g_xt);
    cudaGetSymbolAddress((void**)&q, g_q);
    cudaGetSymbolAddress((void**)&k, g_k);
    cudaGetSymbolAddress((void**)&v, g_v);
    cudaGetSymbolAddress((void**)&rp_st, g_rp_st);
    cudaGetSymbolAddress((void**)&col_st, g_col_st);
    cudaGetSymbolAddress((void**)&rp_ts, g_rp_ts);
    cudaGetSymbolAddress((void**)&col_ts, g_col_ts);
    cudaGetSymbolAddress((void**)&cnt, g_cnt);

    float* xs0 = xsA;
    float* xs1 = xsA + NSRC * 64;
    float* xt0 = xtA;
    float* xt1 = xtA + NTGT * 64;

    // initial node features (identity gather per node_id arrays)
    k_gather<<<(NSRC * 16 + 255) / 256, 256>>>(src_emb, nid_s, xs0, NSRC);
    k_gather<<<(NTGT * 16 + 255) / 256, 256>>>(tgt_emb, nid_t, xt0, NTGT);

    // CSR for edge_st (group by dst in [0, NTGT))
    k_zero_int<<<(NTGT + 255) / 256, 256>>>(cnt, NTGT);
    k_count<<<(EE + 255) / 256, 256>>>(e_st + EE, cnt, EE);
    k_scan<<<1, 1024>>>(cnt, rp_st, NTGT);
    k_copy_int<<<(NTGT + 255) / 256, 256>>>(rp_st, cnt, NTGT);
    k_scatter<<<(EE + 255) / 256, 256>>>(e_st, e_st + EE, cnt, col_st, EE);

    // CSR for edge_ts (group by dst in [0, NSRC))
    k_zero_int<<<(NSRC + 255) / 256, 256>>>(cnt, NSRC);
    k_count<<<(EE + 255) / 256, 256>>>(e_ts + EE, cnt, EE);
    k_scan<<<1, 1024>>>(cnt, rp_ts, NSRC);
    k_copy_int<<<(NSRC + 255) / 256, 256>>>(rp_ts, cnt, NSRC);
    k_scatter<<<(EE + 255) / 256, 256>>>(e_ts, e_ts + EE, cnt, col_ts, EE);

    dim3 g256s((NSRC + 63) / 64, 4), g256t((NTGT + 63) / 64, 4);
    dim3 g64s((NSRC + 63) / 64, 1), g64t((NTGT + 63) / 64, 1);

    for (int l = 0; l < 2; l++) {
        float* xs_cur = (l == 0) ? xs0 : xs1;
        float* xt_cur = (l == 0) ? xt0 : xt1;
        float* xs_nxt = (l == 0) ? xs1 : xs0;
        float* xt_nxt = (l == 0) ? xt1 : xt0;
        int relu = (l == 0) ? 1 : 0;
        int p0 = l * 2 + 0, p1 = l * 2 + 1;

        // ---- tconv st: src = xs_cur (NSRC), dst = xt_cur (NTGT), params (l,0) ----
        k_gemm_tc<<<g256s, 128, GEMM_SMEM>>>(xs_cur, NSRC, Wk + p0 * 64 * 256, bk + p0 * 256, k, 256);
        k_gemm_tc<<<g256s, 128, GEMM_SMEM>>>(xs_cur, NSRC, Wv + p0 * 64 * 256, bv + p0 * 256, v, 256);
        k_gemm_tc<<<g256t, 128, GEMM_SMEM>>>(xt_cur, NTGT, Wq + p0 * 64 * 256, bq + p0 * 256, q, 256);
        k_gemm_tc<<<g64t, 128, GEMM_SMEM>>>(xt_cur, NTGT, Ws + p0 * 4096, bs + p0 * 64, xt_nxt, 64);
        k_attn<<<(NTGT + 7) / 8, 256>>>(rp_st, col_st, q, k, v, xt_nxt, NTGT, relu);

        // ---- tconv ts: src = xt_cur (NTGT), dst = xs_cur (NSRC), params (l,1) ----
        k_gemm_tc<<<g256t, 128, GEMM_SMEM>>>(xt_cur, NTGT, Wk + p1 * 64 * 256, bk + p1 * 256, k, 256);
        k_gemm_tc<<<g256t, 128, GEMM_SMEM>>>(xt_cur, NTGT, Wv + p1 * 64 * 256, bv + p1 * 256, v, 256);
        k_gemm_tc<<<g256s, 128, GEMM_SMEM>>>(xs_cur, NSRC, Wq + p1 * 64 * 256, bq + p1 * 256, q, 256);
        k_gemm_tc<<<g64s, 128, GEMM_SMEM>>>(xs_cur, NSRC, Ws + p1 * 4096, bs + p1 * 64, xs_nxt, 64);
        k_attn<<<(NSRC + 7) / 8, 256>>>(rp_ts, col_ts, q, k, v, xs_nxt, NSRC, relu);
    }

    // after l=1 the final features live in buffer 0
    k_classify<<<(NLBL + 255) / 256, 256>>>(xs0, xt0, lbl, outp, NLBL);
}

// round 4
// speedup vs baseline: 1.0944x; 1.0690x over previous
#include <cuda_runtime.h>
#include <cuda_bf16.h>
#include <cstdint>

#define NSRC 50000
#define NTGT 10000
#define EE   250000
#define NLBL 200000
#define PW   832     // packed width: K(256)|V(256)|Q(256)|S(64)

// ---------------- scratch (static device globals; no runtime allocation) ----------------
__device__ float g_xs[2][NSRC * 64];
__device__ float g_xt[2][NTGT * 64];
__device__ float g_xsP[NSRC * PW];
__device__ float g_xtP[NTGT * PW];
__device__ float g_WpS[2 * 64 * PW];
__device__ float g_WpT[2 * 64 * PW];
__device__ float g_bpS[2 * PW];
__device__ float g_bpT[2 * PW];
__device__ int   g_rp_st[NTGT + 1];
__device__ int   g_col_st[EE];
__device__ int   g_rp_ts[NSRC + 1];
__device__ int   g_col_ts[EE];
__device__ int   g_cnt[NSRC];

// ---------------- helpers ----------------
// pack two fp32 -> bf16x2 (first arg -> upper 16 bits, second -> lower)
__device__ __forceinline__ uint32_t bfpack(float hi, float lo) {
    uint32_t u;
    asm("cvt.rn.bf16x2.f32 %0, %1, %2;" : "=r"(u) : "f"(hi), "f"(lo));
    return u;
}
__device__ __forceinline__ float bfr(float x) {   // round to bf16, back to f32
    return __bfloat162float(__float2bfloat16(x));
}
__device__ __forceinline__ void mma_bf16(float* c, const uint32_t* a, const uint32_t* b) {
    asm volatile(
        "mma.sync.aligned.m16n8k16.row.col.f32.bf16.bf16.f32 "
        "{%0,%1,%2,%3}, {%4,%5,%6,%7}, {%8,%9}, {%0,%1,%2,%3};"
        : "+f"(c[0]), "+f"(c[1]), "+f"(c[2]), "+f"(c[3])
        : "r"(a[0]), "r"(a[1]), "r"(a[2]), "r"(a[3]), "r"(b[0]), "r"(b[1]));
}

// ---------------- small utility kernels ----------------
__global__ void k_gather(const float* __restrict__ emb, const int* __restrict__ ids,
                         float* __restrict__ out, int nrows) {
    int t = blockIdx.x * blockDim.x + threadIdx.x;
    int total = nrows * 16;
    if (t >= total) return;
    int r = t >> 4, c = t & 15;
    ((float4*)out)[r * 16 + c] = ((const float4*)emb)[ids[r] * 16 + c];
}

__global__ void k_zero_int(int* p, int n) {
    int t = blockIdx.x * blockDim.x + threadIdx.x;
    if (t < n) p[t] = 0;
}

__global__ void k_copy_int(const int* __restrict__ a, int* __restrict__ b, int n) {
    int t = blockIdx.x * blockDim.x + threadIdx.x;
    if (t < n) b[t] = a[t];
}

__global__ void k_count(const int* __restrict__ dst, int* cnt, int E) {
    int t = blockIdx.x * blockDim.x + threadIdx.x;
    if (t < E) atomicAdd(&cnt[dst[t]], 1);
}

__global__ void k_scan(const int* __restrict__ deg, int* __restrict__ rowptr, int n) {
    __shared__ int warpsums[32];
    __shared__ int sbase;
    int tid = threadIdx.x, lane = tid & 31, wid = tid >> 5;
    if (tid == 0) sbase = 0;
    __syncthreads();
    for (int chunk = 0; chunk < n; chunk += 1024) {
        int i = chunk + tid;
        int v = (i < n) ? deg[i] : 0;
        int x = v;
#pragma unroll
        for (int off = 1; off < 32; off <<= 1) {
            int y = __shfl_up_sync(0xffffffffu, x, off);
            if (lane >= off) x += y;
        }
        if (lane == 31) warpsums[wid] = x;
        __syncthreads();
        if (wid == 0) {
            int s = warpsums[lane];
#pragma unroll
            for (int off = 1; off < 32; off <<= 1) {
                int y = __shfl_up_sync(0xffffffffu, s, off);
                if (lane >= off) s += y;
            }
            warpsums[lane] = s;
        }
        __syncthreads();
        int wbase = (wid > 0) ? warpsums[wid - 1] : 0;
        if (i < n) rowptr[i] = sbase + wbase + x - v;
        int total = warpsums[31];
        __syncthreads();
        if (tid == 0) sbase += total;
        __syncthreads();
    }
    if (tid == 0) rowptr[n] = sbase;
}

__global__ void k_scatter(const int* __restrict__ src, const int* __restrict__ dst,
                          int* cursor, int* __restrict__ colout, int E) {
    int t = blockIdx.x * blockDim.x + threadIdx.x;
    if (t < E) {
        int d = dst[t];
        int pos = atomicAdd(&cursor[d], 1);
        colout[pos] = src[t];
    }
}

// ---------------- weight/bias packing ----------------
__global__ void k_packw(const float* __restrict__ Wq, const float* __restrict__ Wk,
                        const float* __restrict__ Wv, const float* __restrict__ Ws) {
    int t = blockIdx.x * blockDim.x + threadIdx.x;
    const int TOT = 2 * 2 * 64 * PW;
    if (t >= TOT) return;
    int side = t / (2 * 64 * PW);
    int r = t % (2 * 64 * PW);
    int l = r / (64 * PW);
    int r2 = r % (64 * PW);
    int k = r2 / PW, n = r2 % PW;
    int e_kv = side ? 1 : 0;
    int e_qs = side ? 0 : 1;
    float v;
    if (n < 256)      v = Wk[(l * 2 + e_kv) * 16384 + k * 256 + n];
    else if (n < 512) v = Wv[(l * 2 + e_kv) * 16384 + k * 256 + (n - 256)];
    else if (n < 768) v = Wq[(l * 2 + e_qs) * 16384 + k * 256 + (n - 512)];
    else              v = Ws[(l * 2 + e_qs) * 4096 + k * 64 + (n - 768)];
    float* dst = side ? g_WpT : g_WpS;
    dst[(l * 64 + k) * PW + n] = v;
}

__global__ void k_packb(const float* __restrict__ bq, const float* __restrict__ bk,
                        const float* __restrict__ bv, const float* __restrict__ bs) {
    int t = blockIdx.x * blockDim.x + threadIdx.x;
    const int TOT = 2 * 2 * PW;
    if (t >= TOT) return;
    int side = t / (2 * PW);
    int r = t % (2 * PW);
    int l = r / PW, n = r % PW;
    int e_kv = side ? 1 : 0;
    int e_qs = side ? 0 : 1;
    float v;
    if (n < 256)      v = bk[(l * 2 + e_kv) * 256 + n];
    else if (n < 512) v = bv[(l * 2 + e_kv) * 256 + (n - 256)];
    else if (n < 768) v = bq[(l * 2 + e_qs) * 256 + (n - 512)];
    else              v = bs[(l * 2 + e_qs) * 64 + (n - 768)];
    float* dst = side ? g_bpT : g_bpS;
    dst[l * PW + n] = v;
}

// ---------------- HMMA bf16 GEMM (3xBF16): C[rows,832] = X[rows,64] @ Wp[64,832] + b ----
// block: 256 threads (8 warps), tile M=128 (16 rows/warp), N=64 per blockIdx.y, K=64.
// smem: sA[128][33] uint2 {hi_pack, lo_pack} (k-pairs), sB[64][33] uint2.
#define SA_STRIDE 33
#define GB_SMEM ((128 + 64) * SA_STRIDE * (int)sizeof(uint2))
__global__ __launch_bounds__(256) void k_gemm_h(
    const float* __restrict__ X, int Nrows,
    const float* __restrict__ Wp, const float* __restrict__ bp,
    float* __restrict__ C) {
    extern __shared__ unsigned char raw[];
    uint2* sA = (uint2*)raw;                       // [128][33]
    uint2* sB = sA + 128 * SA_STRIDE;              // [64][33]
    int tid = threadIdx.x;
    int row0 = blockIdx.x << 7, col0 = blockIdx.y << 6;

    // stage A: X tile [128 x 64], hi/lo bf16 split packed along k
#pragma unroll
    for (int i = 0; i < 8; i++) {
        int s4 = tid + (i << 8);                   // 0..2047 float4 slots
        int r = s4 >> 4, c = s4 & 15;              // c: float4 index (4 k values)
        float4 xv = make_float4(0.f, 0.f, 0.f, 0.f);
        if (row0 + r < Nrows) xv = *(const float4*)(X + (size_t)(row0 + r) * 64 + (c << 2));
        float h0 = bfr(xv.x), h1 = bfr(xv.y), h2 = bfr(xv.z), h3 = bfr(xv.w);
        sA[r * SA_STRIDE + (c << 1)]     = make_uint2(bfpack(h1, h0), bfpack(xv.y - h1, xv.x - h0));
        sA[r * SA_STRIDE + (c << 1) + 1] = make_uint2(bfpack(h3, h2), bfpack(xv.w - h3, xv.z - h2));
    }
    // stage B: sB[n][p] from Wp[k=2p..2p+1][col0+n]
#pragma unroll
    for (int i = 0; i < 8; i++) {
        int idx = tid + (i << 8);                  // 0..2047
        int n = idx & 63, p = idx >> 6;            // p in [0,32)
        const float* wp = Wp + (size_t)(p * 2) * PW + col0 + n;
        float w0 = wp[0], w1 = wp[PW];
        float hw0 = bfr(w0), hw1 = bfr(w1);
        sB[n * SA_STRIDE + p] = make_uint2(bfpack(hw1, hw0), bfpack(w1 - hw1, w0 - hw0));
    }
    __syncthreads();

    int lane = tid & 31, warp = tid >> 5;
    int gid = lane >> 2, tig = lane & 3;
    int m0 = warp << 4;

    float acc[8][4];
#pragma unroll
    for (int nt = 0; nt < 8; nt++)
#pragma unroll
        for (int j = 0; j < 4; j++) acc[nt][j] = 0.f;

#pragma unroll
    for (int kk = 0; kk < 4; kk++) {
        int k0h = kk << 3;                         // pair offset for this k16 step
        uint2 a00 = sA[(m0 + gid) * SA_STRIDE + k0h + tig];
        uint2 a01 = sA[(m0 + gid + 8) * SA_STRIDE + k0h + tig];
        uint2 a10 = sA[(m0 + gid) * SA_STRIDE + k0h + tig + 4];
        uint2 a11 = sA[(m0 + gid + 8) * SA_STRIDE + k0h + tig + 4];
        uint32_t ahi[4] = { a00.x, a01.x, a10.x, a11.x };
        uint32_t alo[4] = { a00.y, a01.y, a10.y, a11.y };
#pragma unroll
        for (int nt = 0; nt < 8; nt++) {
            uint2 b0 = sB[((nt << 3) + gid) * SA_STRIDE + k0h + tig];
            uint2 b1 = sB[((nt << 3) + gid) * SA_STRIDE + k0h + tig + 4];
            uint32_t bhi[2] = { b0.x, b1.x };
            uint32_t blo[2] = { b0.y, b1.y };
            mma_bf16(acc[nt], ahi, bhi);
            mma_bf16(acc[nt], alo, bhi);
            mma_bf16(acc[nt], ahi, blo);
        }
    }

    // epilogue: + bias, store (c0,c1 -> row gid; c2,c3 -> row gid+8; cols 2tig,2tig+1)
#pragma unroll
    for (int nt = 0; nt < 8; nt++) {
        int col = col0 + (nt << 3) + (tig << 1);
        float2 bias = *(const float2*)(bp + col);
        int r = row0 + m0 + gid;
        if (r < Nrows) {
            *(float2*)(C + (size_t)r * PW + col) =
                make_float2(acc[nt][0] + bias.x, acc[nt][1] + bias.y);
        }
        r += 8;
        if (r < Nrows) {
            *(float2*)(C + (size_t)r * PW + col) =
                make_float2(acc[nt][2] + bias.x, acc[nt][3] + bias.y);
        }
    }
}

// ---------------- fused per-dst attention ----------------
// Packed rows: K at +0, V at +256, Q at +512, skip at +768, stride 832.
__global__ void k_attn(const int* __restrict__ rowptr, const int* __restrict__ col,
                       const float* __restrict__ srcP, const float* __restrict__ dstP,
                       float* __restrict__ out, int ndst, int do_relu) {
    int w = (blockIdx.x * blockDim.x + threadIdx.x) >> 5;
    if (w >= ndst) return;
    int lane = threadIdx.x & 31;

    const float4* qp = (const float4*)(dstP + (size_t)w * PW + 512 + lane * 8);
    float4 q0 = qp[0], q1 = qp[1];

    float a0 = 0.f, a1 = 0.f, a2 = 0.f, a3 = 0.f, a4 = 0.f, a5 = 0.f, a6 = 0.f, a7 = 0.f;
    float denom = 0.f;
    int e0 = rowptr[w], e1 = rowptr[w + 1];
    int e = e0;

#define EDGE_BODY(S, WGT)                                                        \
    {   const float4* kp = (const float4*)(srcP + (size_t)(S) * PW + lane * 8);  \
        const float4* vp = (const float4*)(srcP + (size_t)(S) * PW + 256 + lane * 8); \
        float4 k0 = kp[0], k1 = kp[1];                                           \
        float4 v0 = vp[0], v1 = vp[1];                                           \
        float p = q0.x * k0.x + q0.y * k0.y + q0.z * k0.z + q0.w * k0.w          \
                + q1.x * k1.x + q1.y * k1.y + q1.z * k1.z + q1.w * k1.w;         \
        p += __shfl_xor_sync(0xffffffffu, p, 1);                                 \
        p += __shfl_xor_sync(0xffffffffu, p, 2);                                 \
        p += __shfl_xor_sync(0xffffffffu, p, 4);                                 \
        float WGT = __expf(p * 0.125f);                                          \
        denom += WGT;                                                            \
        a0 += WGT * v0.x; a1 += WGT * v0.y; a2 += WGT * v0.z; a3 += WGT * v0.w;  \
        a4 += WGT * v1.x; a5 += WGT * v1.y; a6 += WGT * v1.z; a7 += WGT * v1.w; }

    for (; e + 2 <= e1; e += 2) {
        int s0 = col[e], s1 = col[e + 1];
        EDGE_BODY(s0, wg0)
        EDGE_BODY(s1, wg1)
    }
    if (e < e1) { int s0 = col[e]; EDGE_BODY(s0, wg2) }
#undef EDGE_BODY

    float inv = (denom > 0.f) ? (0.25f / denom) : 0.f;
    a0 *= inv; a1 *= inv; a2 *= inv; a3 *= inv;
    a4 *= inv; a5 *= inv; a6 *= inv; a7 *= inv;

#define HEADRED(x) x += __shfl_xor_sync(0xffffffffu, x, 8); x += __shfl_xor_sync(0xffffffffu, x, 16);
    HEADRED(a0) HEADRED(a1) HEADRED(a2) HEADRED(a3)
    HEADRED(a4) HEADRED(a5) HEADRED(a6) HEADRED(a7)
#undef HEADRED

    if (lane < 8) {
        const float* sp = dstP + (size_t)w * PW + 768 + lane * 8;
        float* op = out + (size_t)w * 64 + lane * 8;
        float r[8] = {a0, a1, a2, a3, a4, a5, a6, a7};
#pragma unroll
        for (int j = 0; j < 8; j++) {
            float val = r[j] + sp[j];
            if (do_relu) val = fmaxf(val, 0.f);
            op[j] = val;
        }
    }
}

// ---------------- classifier ----------------
__global__ void k_classify(const float* __restrict__ xs, const float* __restrict__ xt,
                           const int* __restrict__ li, float* __restrict__ out, int n) {
    int t = blockIdx.x * blockDim.x + threadIdx.x;
    if (t >= n) return;
    int a = li[t], b = li[n + t];
    const float4* pa = (const float4*)(xs + (size_t)a * 64);
    const float4* pb = (const float4*)(xt + (size_t)b * 64);
    float s = 0.f;
#pragma unroll
    for (int j = 0; j < 16; j++) {
        float4 x = pa[j], y = pb[j];
        s += x.x * y.x + x.y * y.y + x.z * y.z + x.w * y.w;
    }
    out[t] = s;
}

// ---------------- launch ----------------
extern "C" void kernel_launch(void* const* d_in, const int* in_sizes, int n_in,
                              void* d_out, int out_size) {
    const float* src_emb = (const float*)d_in[0];
    const float* tgt_emb = (const float*)d_in[1];
    const float* Wq = (const float*)d_in[2];
    const float* bq = (const float*)d_in[3];
    const float* Wk = (const float*)d_in[4];
    const float* bk = (const float*)d_in[5];
    const float* Wv = (const float*)d_in[6];
    const float* bv = (const float*)d_in[7];
    const float* Ws = (const float*)d_in[8];
    const float* bs = (const float*)d_in[9];
    const int* nid_s = (const int*)d_in[10];
    const int* nid_t = (const int*)d_in[11];
    const int* e_st = (const int*)d_in[12];
    const int* e_ts = (const int*)d_in[13];
    const int* lbl  = (const int*)d_in[14];
    float* outp = (float*)d_out;

    static int attr_done = 0;
    if (!attr_done) {
        cudaFuncSetAttribute(k_gemm_h, cudaFuncAttributeMaxDynamicSharedMemorySize, GB_SMEM);
        attr_done = 1;
    }

    float *xsA, *xtA, *xsP, *xtP, *WpS, *WpT, *bpS, *bpT;
    int *rp_st, *col_st, *rp_ts, *col_ts, *cnt;
    cudaGetSymbolAddress((void**)&xsA, g_xs);
    cudaGetSymbolAddress((void**)&xtA, g_xt);
    cudaGetSymbolAddress((void**)&xsP, g_xsP);
    cudaGetSymbolAddress((void**)&xtP, g_xtP);
    cudaGetSymbolAddress((void**)&WpS, g_WpS);
    cudaGetSymbolAddress((void**)&WpT, g_WpT);
    cudaGetSymbolAddress((void**)&bpS, g_bpS);
    cudaGetSymbolAddress((void**)&bpT, g_bpT);
    cudaGetSymbolAddress((void**)&rp_st, g_rp_st);
    cudaGetSymbolAddress((void**)&col_st, g_col_st);
    cudaGetSymbolAddress((void**)&rp_ts, g_rp_ts);
    cudaGetSymbolAddress((void**)&col_ts, g_col_ts);
    cudaGetSymbolAddress((void**)&cnt, g_cnt);

    float* xs0 = xsA;
    float* xs1 = xsA + NSRC * 64;
    float* xt0 = xtA;
    float* xt1 = xtA + NTGT * 64;

    dim3 gs((NSRC + 127) / 128, 13), gt((NTGT + 127) / 128, 13);

    // 1-2: pack weights/biases
    k_packw<<<(2 * 2 * 64 * PW + 255) / 256, 256>>>(Wq, Wk, Wv, Ws);
    k_packb<<<(2 * 2 * PW + 255) / 256, 256>>>(bq, bk, bv, bs);
    // 3-4: tgt side gather + GEMM
    k_gather<<<(NTGT * 16 + 255) / 256, 256>>>(tgt_emb, nid_t, xt0, NTGT);
    k_gemm_h<<<gt, 256, GB_SMEM>>>(xt0, NTGT, WpT, bpT, xtP);
    // 5-6: src side gather + GEMM  (launch #6 -> ncu -s 5 -c 1 target)
    k_gather<<<(NSRC * 16 + 255) / 256, 256>>>(src_emb, nid_s, xs0, NSRC);
    k_gemm_h<<<gs, 256, GB_SMEM>>>(xs0, NSRC, WpS, bpS, xsP);

    // CSR st
    k_zero_int<<<(NTGT + 255) / 256, 256>>>(cnt, NTGT);
    k_count<<<(EE + 255) / 256, 256>>>(e_st + EE, cnt, EE);
    k_scan<<<1, 1024>>>(cnt, rp_st, NTGT);
    k_copy_int<<<(NTGT + 255) / 256, 256>>>(rp_st, cnt, NTGT);
    k_scatter<<<(EE + 255) / 256, 256>>>(e_st, e_st + EE, cnt, col_st, EE);
    // CSR ts
    k_zero_int<<<(NSRC + 255) / 256, 256>>>(cnt, NSRC);
    k_count<<<(EE + 255) / 256, 256>>>(e_ts + EE, cnt, EE);
    k_scan<<<1, 1024>>>(cnt, rp_ts, NSRC);
    k_copy_int<<<(NSRC + 255) / 256, 256>>>(rp_ts, cnt, NSRC);
    k_scatter<<<(EE + 255) / 256, 256>>>(e_ts, e_ts + EE, cnt, col_ts, EE);

    // layer 0 attention (relu)
    k_attn<<<(NTGT + 7) / 8, 256>>>(rp_st, col_st, xsP, xtP, xt1, NTGT, 1);
    k_attn<<<(NSRC + 7) / 8, 256>>>(rp_ts, col_ts, xtP, xsP, xs1, NSRC, 1);

    // layer 1
    k_gemm_h<<<gs, 256, GB_SMEM>>>(xs1, NSRC, WpS + 64 * PW, bpS + PW, xsP);
    k_gemm_h<<<gt, 256, GB_SMEM>>>(xt1, NTGT, WpT + 64 * PW, bpT + PW, xtP);
    k_attn<<<(NTGT + 7) / 8, 256>>>(rp_st, col_st, xsP, xtP, xt0, NTGT, 0);
    k_attn<<<(NSRC + 7) / 8, 256>>>(rp_ts, col_ts, xtP, xsP, xs0, NSRC, 0);

    k_classify<<<(NLBL + 255) / 256, 256>>>(xs0, xt0, lbl, outp, NLBL);
}

// round 5
// speedup vs baseline: 1.1546x; 1.0550x over previous
#include <cuda_runtime.h>
#include <cuda_bf16.h>
#include <cstdint>

#define NSRC 50000
#define NTGT 10000
#define EE   250000
#define NLBL 200000
#define PW   832     // packed width: K(256)|V(256)|Q(256)|S(64)
#define NT8  104     // PW/8 sub-tiles

// ---------------- scratch (static device globals; no runtime allocation) ----------------
__device__ float g_xs[2][NSRC * 64];
__device__ float g_xt[2][NTGT * 64];
__device__ float g_xsP[NSRC * PW];
__device__ float g_xtP[NTGT * PW];
__device__ uint4 g_Wfrag[2][2][NT8][4][32];   // [side][layer][T][kstep][lane]
__device__ float g_bpS[2 * PW];
__device__ float g_bpT[2 * PW];
__device__ int   g_rp_st[NTGT + 1];
__device__ int   g_col_st[EE];
__device__ int   g_rp_ts[NSRC + 1];
__device__ int   g_col_ts[EE];
__device__ int   g_cnt[NSRC];

// ---------------- helpers ----------------
__device__ __forceinline__ uint32_t bfpack(float hi, float lo) {
    uint32_t u;
    asm("cvt.rn.bf16x2.f32 %0, %1, %2;" : "=r"(u) : "f"(hi), "f"(lo));
    return u;
}
__device__ __forceinline__ float bfr(float x) {
    return __bfloat162float(__float2bfloat16(x));
}
__device__ __forceinline__ void mma_bf16(float* c, const uint32_t* a, const uint32_t* b) {
    asm volatile(
        "mma.sync.aligned.m16n8k16.row.col.f32.bf16.bf16.f32 "
        "{%0,%1,%2,%3}, {%4,%5,%6,%7}, {%8,%9}, {%0,%1,%2,%3};"
        : "+f"(c[0]), "+f"(c[1]), "+f"(c[2]), "+f"(c[3])
        : "r"(a[0]), "r"(a[1]), "r"(a[2]), "r"(a[3]), "r"(b[0]), "r"(b[1]));
}

// ---------------- small utility kernels ----------------
__global__ void k_gather(const float* __restrict__ emb, const int* __restrict__ ids,
                         float* __restrict__ out, int nrows) {
    int t = blockIdx.x * blockDim.x + threadIdx.x;
    int total = nrows * 16;
    if (t >= total) return;
    int r = t >> 4, c = t & 15;
    ((float4*)out)[r * 16 + c] = ((const float4*)emb)[ids[r] * 16 + c];
}

__global__ void k_zero_int(int* p, int n) {
    int t = blockIdx.x * blockDim.x + threadIdx.x;
    if (t < n) p[t] = 0;
}

__global__ void k_copy_int(const int* __restrict__ a, int* __restrict__ b, int n) {
    int t = blockIdx.x * blockDim.x + threadIdx.x;
    if (t < n) b[t] = a[t];
}

__global__ void k_count(const int* __restrict__ dst, int* cnt, int E) {
    int t = blockIdx.x * blockDim.x + threadIdx.x;
    if (t < E) atomicAdd(&cnt[dst[t]], 1);
}

__global__ void k_scan(const int* __restrict__ deg, int* __restrict__ rowptr, int n) {
    __shared__ int warpsums[32];
    __shared__ int sbase;
    int tid = threadIdx.x, lane = tid & 31, wid = tid >> 5;
    if (tid == 0) sbase = 0;
    __syncthreads();
    for (int chunk = 0; chunk < n; chunk += 1024) {
        int i = chunk + tid;
        int v = (i < n) ? deg[i] : 0;
        int x = v;
#pragma unroll
        for (int off = 1; off < 32; off <<= 1) {
            int y = __shfl_up_sync(0xffffffffu, x, off);
            if (lane >= off) x += y;
        }
        if (lane == 31) warpsums[wid] = x;
        __syncthreads();
        if (wid == 0) {
            int s = warpsums[lane];
#pragma unroll
            for (int off = 1; off < 32; off <<= 1) {
                int y = __shfl_up_sync(0xffffffffu, s, off);
                if (lane >= off) s += y;
            }
            warpsums[lane] = s;
        }
        __syncthreads();
        int wbase = (wid > 0) ? warpsums[wid - 1] : 0;
        if (i < n) rowptr[i] = sbase + wbase + x - v;
        int total = warpsums[31];
        __syncthreads();
        if (tid == 0) sbase += total;
        __syncthreads();
    }
    if (tid == 0) rowptr[n] = sbase;
}

__global__ void k_scatter(const int* __restrict__ src, const int* __restrict__ dst,
                          int* cursor, int* __restrict__ colout, int E) {
    int t = blockIdx.x * blockDim.x + threadIdx.x;
    if (t < E) {
        int d = dst[t];
        int pos = atomicAdd(&cursor[d], 1);
        colout[pos] = src[t];
    }
}

// ---------------- weight packing into mma-fragment order, pre-split hi/lo bf16 ----------
// One thread per (side, layer, T, kstep, lane). Output uint4 {hi_a, lo_a, hi_b, lo_b}:
// pair a = kk*8+tig (k = 2pa, 2pa+1), pair b = pa+4, column n = T*8+gid.
__global__ void k_packw(const float* __restrict__ Wq, const float* __restrict__ Wk,
                        const float* __restrict__ Wv, const float* __restrict__ Ws) {
    int t = blockIdx.x * blockDim.x + threadIdx.x;
    const int TOT = 2 * 2 * NT8 * 4 * 32;
    if (t >= TOT) return;
    int lane = t & 31;
    int r = t >> 5;
    int kk = r & 3; r >>= 2;
    int T = r % NT8; r /= NT8;
    int l = r & 1;
    int side = r >> 1;
    int gid = lane >> 2, tig = lane & 3;
    int n = T * 8 + gid;
    int e_kv = side ? 1 : 0;
    int e_qs = side ? 0 : 1;

    int pa = kk * 8 + tig;
    float w[4];
#pragma unroll
    for (int j = 0; j < 4; j++) {
        int k = (j < 2) ? (2 * pa + j) : (2 * (pa + 4) + (j - 2));
        float v;
        if (n < 256)      v = Wk[(l * 2 + e_kv) * 16384 + k * 256 + n];
        else if (n < 512) v = Wv[(l * 2 + e_kv) * 16384 + k * 256 + (n - 256)];
        else if (n < 768) v = Wq[(l * 2 + e_qs) * 16384 + k * 256 + (n - 512)];
        else              v = Ws[(l * 2 + e_qs) * 4096 + k * 64 + (n - 768)];
        w[j] = v;
    }
    float h0 = bfr(w[0]), h1 = bfr(w[1]), h2 = bfr(w[2]), h3 = bfr(w[3]);
    uint4 o;
    o.x = bfpack(h1, h0);
    o.y = bfpack(w[1] - h1, w[0] - h0);
    o.z = bfpack(h3, h2);
    o.w = bfpack(w[3] - h3, w[2] - h2);
    g_Wfrag[side][l][T][kk][lane] = o;
}

__global__ void k_packb(const float* __restrict__ bq, const float* __restrict__ bk,
                        const float* __restrict__ bv, const float* __restrict__ bs) {
    int t = blockIdx.x * blockDim.x + threadIdx.x;
    const int TOT = 2 * 2 * PW;
    if (t >= TOT) return;
    int side = t / (2 * PW);
    int r = t % (2 * PW);
    int l = r / PW, n = r % PW;
    int e_kv = side ? 1 : 0;
    int e_qs = side ? 0 : 1;
    float v;
    if (n < 256)      v = bk[(l * 2 + e_kv) * 256 + n];
    else if (n < 512) v = bv[(l * 2 + e_kv) * 256 + (n - 256)];
    else if (n < 768) v = bq[(l * 2 + e_qs) * 256 + (n - 512)];
    else              v = bs[(l * 2 + e_qs) * 64 + (n - 768)];
    float* dst = side ? g_bpT : g_bpS;
    dst[l * PW + n] = v;
}

// ---------------- register-resident HMMA GEMM (3xBF16, no smem) ----------------
// block: 256 threads (8 warps), M=128/block (m16 per warp). grid.y splits the 104
// n-subtiles. A fragments built once in registers; B via coalesced LDG.128 of
// pre-split fragment buffer; 3 independent acc chains per subtile.
__global__ __launch_bounds__(256) void k_gemm_f(
    const float* __restrict__ X, int Nrows,
    const uint4* __restrict__ Bfrag, const float* __restrict__ bp,
    float* __restrict__ C, int nysplit) {
    int tid = threadIdx.x, warp = tid >> 5, lane = tid & 31;
    int gid = lane >> 2, tig = lane & 3;
    int row0 = blockIdx.x << 7;
    int r1 = row0 + (warp << 4) + gid, r2 = r1 + 8;
    bool v1 = r1 < Nrows, v2 = r2 < Nrows;

    // build A fragments (hi/lo bf16 split) in registers
    uint32_t Ah[4][4], Al[4][4];
#pragma unroll
    for (int kk = 0; kk < 4; kk++) {
        float2 xa1 = make_float2(0.f, 0.f), xa2 = xa1, xb1 = xa1, xb2 = xa1;
        int pa = kk * 8 + tig, pb = pa + 4;
        if (v1) { xa1 = *(const float2*)(X + (size_t)r1 * 64 + pa * 2);
                  xb1 = *(const float2*)(X + (size_t)r1 * 64 + pb * 2); }
        if (v2) { xa2 = *(const float2*)(X + (size_t)r2 * 64 + pa * 2);
                  xb2 = *(const float2*)(X + (size_t)r2 * 64 + pb * 2); }
        float h;
        h = bfr(xa1.x); float h2_ = bfr(xa1.y);
        Ah[kk][0] = bfpack(h2_, h); Al[kk][0] = bfpack(xa1.y - h2_, xa1.x - h);
        h = bfr(xa2.x); h2_ = bfr(xa2.y);
        Ah[kk][1] = bfpack(h2_, h); Al[kk][1] = bfpack(xa2.y - h2_, xa2.x - h);
        h = bfr(xb1.x); h2_ = bfr(xb1.y);
        Ah[kk][2] = bfpack(h2_, h); Al[kk][2] = bfpack(xb1.y - h2_, xb1.x - h);
        h = bfr(xb2.x); h2_ = bfr(xb2.y);
        Ah[kk][3] = bfpack(h2_, h); Al[kk][3] = bfpack(xb2.y - h2_, xb2.x - h);
    }

    int Tcount = NT8 / nysplit;
    int Tbeg = blockIdx.y * Tcount;

#define LOADB(dst, T)                                                   \
    {   const uint4* p_ = Bfrag + ((size_t)(T) * 4) * 32 + lane;        \
        dst[0] = __ldg(p_); dst[1] = __ldg(p_ + 32);                    \
        dst[2] = __ldg(p_ + 64); dst[3] = __ldg(p_ + 96); }

#define COMPUTE(T, bb)                                                  \
    {   float aA[4] = {0.f, 0.f, 0.f, 0.f};                             \
        float aB[4] = {0.f, 0.f, 0.f, 0.f};                             \
        float aC[4] = {0.f, 0.f, 0.f, 0.f};                             \
        _Pragma("unroll")                                               \
        for (int kk = 0; kk < 4; kk++) {                                \
            uint32_t bhi[2] = { bb[kk].x, bb[kk].z };                   \
            uint32_t blo[2] = { bb[kk].y, bb[kk].w };                   \
            mma_bf16(aA, Ah[kk], bhi);                                  \
            mma_bf16(aB, Al[kk], bhi);                                  \
            mma_bf16(aC, Ah[kk], blo);                                  \
        }                                                               \
        int col = ((T) << 3) + (tig << 1);                              \
        float2 bias = *(const float2*)(bp + col);                       \
        if (v1) *(float2*)(C + (size_t)r1 * PW + col) = make_float2(    \
            aA[0] + aB[0] + aC[0] + bias.x, aA[1] + aB[1] + aC[1] + bias.y); \
        if (v2) *(float2*)(C + (size_t)r2 * PW + col) = make_float2(    \
            aA[2] + aB[2] + aC[2] + bias.x, aA[3] + aB[3] + aC[3] + bias.y); }

    uint4 b0[4], b1[4];
    LOADB(b0, Tbeg)
    for (int T = Tbeg; T < Tbeg + Tcount; T += 2) {
        LOADB(b1, T + 1)
        COMPUTE(T, b0)
        if (T + 2 < Tbeg + Tcount) LOADB(b0, T + 2)
        COMPUTE(T + 1, b1)
    }
#undef LOADB
#undef COMPUTE
}

// ---------------- fused per-dst attention ----------------
// Packed rows: K at +0, V at +256, Q at +512, skip at +768, stride 832.
__global__ void k_attn(const int* __restrict__ rowptr, const int* __restrict__ col,
                       const float* __restrict__ srcP, const float* __restrict__ dstP,
                       float* __restrict__ out, int ndst, int do_relu) {
    int w = (blockIdx.x * blockDim.x + threadIdx.x) >> 5;
    if (w >= ndst) return;
    int lane = threadIdx.x & 31;

    const float4* qp = (const float4*)(dstP + (size_t)w * PW + 512 + lane * 8);
    float4 q0 = qp[0], q1 = qp[1];

    float a0 = 0.f, a1 = 0.f, a2 = 0.f, a3 = 0.f, a4 = 0.f, a5 = 0.f, a6 = 0.f, a7 = 0.f;
    float denom = 0.f;
    int e0 = rowptr[w], e1 = rowptr[w + 1];
    int e = e0;

#define EDGE_BODY(S, WGT)                                                        \
    {   const float4* kp = (const float4*)(srcP + (size_t)(S) * PW + lane * 8);  \
        const float4* vp = (const float4*)(srcP + (size_t)(S) * PW + 256 + lane * 8); \
        float4 k0 = kp[0], k1 = kp[1];                                           \
        float4 v0 = vp[0], v1 = vp[1];                                           \
        float p = q0.x * k0.x + q0.y * k0.y + q0.z * k0.z + q0.w * k0.w          \
                + q1.x * k1.x + q1.y * k1.y + q1.z * k1.z + q1.w * k1.w;         \
        p += __shfl_xor_sync(0xffffffffu, p, 1);                                 \
        p += __shfl_xor_sync(0xffffffffu, p, 2);                                 \
        p += __shfl_xor_sync(0xffffffffu, p, 4);                                 \
        float WGT = __expf(p * 0.125f);                                          \
        denom += WGT;                                                            \
        a0 += WGT * v0.x; a1 += WGT * v0.y; a2 += WGT * v0.z; a3 += WGT * v0.w;  \
        a4 += WGT * v1.x; a5 += WGT * v1.y; a6 += WGT * v1.z; a7 += WGT * v1.w; }

    for (; e + 2 <= e1; e += 2) {
        int s0 = col[e], s1 = col[e + 1];
        EDGE_BODY(s0, wg0)
        EDGE_BODY(s1, wg1)
    }
    if (e < e1) { int s0 = col[e]; EDGE_BODY(s0, wg2) }
#undef EDGE_BODY

    float inv = (denom > 0.f) ? (0.25f / denom) : 0.f;
    a0 *= inv; a1 *= inv; a2 *= inv; a3 *= inv;
    a4 *= inv; a5 *= inv; a6 *= inv; a7 *= inv;

#define HEADRED(x) x += __shfl_xor_sync(0xffffffffu, x, 8); x += __shfl_xor_sync(0xffffffffu, x, 16);
    HEADRED(a0) HEADRED(a1) HEADRED(a2) HEADRED(a3)
    HEADRED(a4) HEADRED(a5) HEADRED(a6) HEADRED(a7)
#undef HEADRED

    if (lane < 8) {
        const float* sp = dstP + (size_t)w * PW + 768 + lane * 8;
        float* op = out + (size_t)w * 64 + lane * 8;
        float r[8] = {a0, a1, a2, a3, a4, a5, a6, a7};
#pragma unroll
        for (int j = 0; j < 8; j++) {
            float val = r[j] + sp[j];
            if (do_relu) val = fmaxf(val, 0.f);
            op[j] = val;
        }
    }
}

// ---------------- classifier ----------------
__global__ void k_classify(const float* __restrict__ xs, const float* __restrict__ xt,
                           const int* __restrict__ li, float* __restrict__ out, int n) {
    int t = blockIdx.x * blockDim.x + threadIdx.x;
    if (t >= n) return;
    int a = li[t], b = li[n + t];
    const float4* pa = (const float4*)(xs + (size_t)a * 64);
    const float4* pb = (const float4*)(xt + (size_t)b * 64);
    float s = 0.f;
#pragma unroll
    for (int j = 0; j < 16; j++) {
        float4 x = pa[j], y = pb[j];
        s += x.x * y.x + x.y * y.y + x.z * y.z + x.w * y.w;
    }
    out[t] = s;
}

// ---------------- launch ----------------
extern "C" void kernel_launch(void* const* d_in, const int* in_sizes, int n_in,
                              void* d_out, int out_size) {
    const float* src_emb = (const float*)d_in[0];
    const float* tgt_emb = (const float*)d_in[1];
    const float* Wq = (const float*)d_in[2];
    const float* bq = (const float*)d_in[3];
    const float* Wk = (const float*)d_in[4];
    const float* bk = (const float*)d_in[5];
    const float* Wv = (const float*)d_in[6];
    const float* bv = (const float*)d_in[7];
    const float* Ws = (const float*)d_in[8];
    const float* bs = (const float*)d_in[9];
    const int* nid_s = (const int*)d_in[10];
    const int* nid_t = (const int*)d_in[11];
    const int* e_st = (const int*)d_in[12];
    const int* e_ts = (const int*)d_in[13];
    const int* lbl  = (const int*)d_in[14];
    float* outp = (float*)d_out;

    float *xsA, *xtA, *xsP, *xtP, *bpS, *bpT;
    uint4* Wfrag;
    int *rp_st, *col_st, *rp_ts, *col_ts, *cnt;
    cudaGetSymbolAddress((void**)&xsA, g_xs);
    cudaGetSymbolAddress((void**)&xtA, g_xt);
    cudaGetSymbolAddress((void**)&xsP, g_xsP);
    cudaGetSymbolAddress((void**)&xtP, g_xtP);
    cudaGetSymbolAddress((void**)&Wfrag, g_Wfrag);
    cudaGetSymbolAddress((void**)&bpS, g_bpS);
    cudaGetSymbolAddress((void**)&bpT, g_bpT);
    cudaGetSymbolAddress((void**)&rp_st, g_rp_st);
    cudaGetSymbolAddress((void**)&col_st, g_col_st);
    cudaGetSymbolAddress((void**)&rp_ts, g_rp_ts);
    cudaGetSymbolAddress((void**)&col_ts, g_col_ts);
    cudaGetSymbolAddress((void**)&cnt, g_cnt);

    float* xs0 = xsA;
    float* xs1 = xsA + NSRC * 64;
    float* xt0 = xtA;
    float* xt1 = xtA + NTGT * 64;

    // fragment buffer offsets: [side][layer] stride = NT8*4*32 uint4
    const size_t WL = (size_t)NT8 * 4 * 32;
    const uint4* WfS0 = Wfrag;                 // side 0, layer 0
    const uint4* WfS1 = Wfrag + WL;            // side 0, layer 1
    const uint4* WfT0 = Wfrag + 2 * WL;        // side 1, layer 0
    const uint4* WfT1 = Wfrag + 3 * WL;

    dim3 gs((NSRC + 127) / 128, 1), gt((NTGT + 127) / 128, 4);

    // 1-2: pack weights (fragment order, pre-split) + biases
    k_packw<<<(2 * 2 * NT8 * 4 * 32 + 255) / 256, 256>>>(Wq, Wk, Wv, Ws);
    k_packb<<<(2 * 2 * PW + 255) / 256, 256>>>(bq, bk, bv, bs);
    // 3-4: tgt side gather + GEMM
    k_gather<<<(NTGT * 16 + 255) / 256, 256>>>(tgt_emb, nid_t, xt0, NTGT);
    k_gemm_f<<<gt, 256>>>(xt0, NTGT, WfT0, bpT, xtP, 4);
    // 5-6: src side gather + GEMM  (launch #6 -> ncu -s 5 -c 1 target)
    k_gather<<<(NSRC * 16 + 255) / 256, 256>>>(src_emb, nid_s, xs0, NSRC);
    k_gemm_f<<<gs, 256>>>(xs0, NSRC, WfS0, bpS, xsP, 1);

    // CSR st
    k_zero_int<<<(NTGT + 255) / 256, 256>>>(cnt, NTGT);
    k_count<<<(EE + 255) / 256, 256>>>(e_st + EE, cnt, EE);
    k_scan<<<1, 1024>>>(cnt, rp_st, NTGT);
    k_copy_int<<<(NTGT + 255) / 256, 256>>>(rp_st, cnt, NTGT);
    k_scatter<<<(EE + 255) / 256, 256>>>(e_st, e_st + EE, cnt, col_st, EE);
    // CSR ts
    k_zero_int<<<(NSRC + 255) / 256, 256>>>(cnt, NSRC);
    k_count<<<(EE + 255) / 256, 256>>>(e_ts + EE, cnt, EE);
    k_scan<<<1, 1024>>>(cnt, rp_ts, NSRC);
    k_copy_int<<<(NSRC + 255) / 256, 256>>>(rp_ts, cnt, NSRC);
    k_scatter<<<(EE + 255) / 256, 256>>>(e_ts, e_ts + EE, cnt, col_ts, EE);

    // layer 0 attention (relu)
    k_attn<<<(NTGT + 7) / 8, 256>>>(rp_st, col_st, xsP, xtP, xt1, NTGT, 1);
    k_attn<<<(NSRC + 7) / 8, 256>>>(rp_ts, col_ts, xtP, xsP, xs1, NSRC, 1);

    // layer 1
    k_gemm_f<<<gs, 256>>>(xs1, NSRC, WfS1, bpS + PW, xsP, 1);
    k_gemm_f<<<gt, 256>>>(xt1, NTGT, WfT1, bpT + PW, xtP, 4);
    k_attn<<<(NTGT + 7) / 8, 256>>>(rp_st, col_st, xsP, xtP, xt0, NTGT, 0);
    k_attn<<<(NSRC + 7) / 8, 256>>>(rp_ts, col_ts, xtP, xsP, xs0, NSRC, 0);

    k_classify<<<(NLBL + 255) / 256, 256>>>(xs0, xt0, lbl, outp, NLBL);
}